// round 14
// baseline (speedup 1.0000x reference)
#include <cuda_runtime.h>
#include <cuda_fp16.h>
#include <cstdint>
#include <cstring>

#define NN   50000
#define DEG  16
#define FDIM 64
#define NE   (NN * DEG)
#define NGRP (NE / 2)          // 128-float drop groups (2 edges each)

// Scratch (allocation-free rule)
__device__ __align__(16) __half2 g_Th[NN * 32];  // T fp16 (lane l: feats 2l,2l+1)
__device__ __align__(16) uint4  g_bxh[NN * 16];  // fp16 {B,x} 16B chunks per node
__device__ __align__(16) uint2  g_xnh[NN * 16];  // x_new fp16
__device__ __align__(16) uint4  g_mb[NGRP];      // drop bitmask: 4 ballots per group
__device__ __align__(16) int    g_nbr[NE];
__device__ int g_is32 = 0;

// ---- packed f32x2 helpers (Blackwell) -------------------------------------
__device__ __forceinline__ unsigned long long pack2(float v) {
    unsigned long long r;
    asm("mov.b64 %0, {%1, %1};" : "=l"(r) : "f"(v));
    return r;
}
__device__ __forceinline__ void fma2(unsigned long long& d,
                                     unsigned long long a, unsigned long long b) {
    asm("fma.rn.f32x2 %0, %1, %2, %0;" : "+l"(d) : "l"(a), "l"(b));
}
__device__ __forceinline__ float2 unpack2(unsigned long long v) {
    float2 f;
    asm("mov.b64 {%0, %1}, %2;" : "=f"(f.x), "=f"(f.y) : "l"(v));
    return f;
}
__device__ __forceinline__ float sigmoid_fast(float z) {
    float t;
    asm("tanh.approx.f32 %0, %1;" : "=f"(t) : "f"(0.5f * z));
    return fmaf(0.5f, t, 0.5f);
}

// ---------------------------------------------------------------------------
// K0: dtype sniff + convert (int64 lo-words vs int32)
// ---------------------------------------------------------------------------
__global__ void k_detect(const int* __restrict__ raw)
{
    int i = (blockIdx.x * blockDim.x + threadIdx.x) * 2 + 1;
    const int lim = NE < (1 << 18) ? NE : (1 << 18);
    for (; i < lim; i += gridDim.x * blockDim.x * 2)
        if (raw[i] != 0) { atomicExch(&g_is32, 1); return; }
}
__global__ void k_convert(const int* __restrict__ raw)
{
    const int is32 = g_is32;
    for (int i = blockIdx.x * blockDim.x + threadIdx.x; i < NE;
         i += gridDim.x * blockDim.x)
        g_nbr[i] = is32 ? raw[i] : raw[2 * i];
}

// ---------------------------------------------------------------------------
// K1 (k_prep): block-role split.
//   even blocks: T = x@wm_top (fp16 out), g_bxh = fp16 {B,x} records.
//   odd blocks : bit-compress drop_mask via warp ballot (values are {0,2}).
// Even/odd interleave puts both roles on each SM per wave so GEMM compute
// hides under the 205 MB drop stream.
// ---------------------------------------------------------------------------
__global__ __launch_bounds__(256, 2)
void k_prep(const float* __restrict__ x, const float* __restrict__ wm,
            const float* __restrict__ drop)
{
    __shared__ float2 sT[FDIM * 32];
    __shared__ float2 sB[FDIM * 32];
    __shared__ float  sx[8][8][FDIM];     // [warp][row][k]

    const int tid  = threadIdx.x;
    const int lane = tid & 31;
    const int wsub = tid >> 5;

    if (blockIdx.x & 1) {
        // ---- compress role (no syncthreads; smem unused) ----
        const int cw = (int)(blockIdx.x >> 1) * 8 + wsub;   // 0..2367
        const float4* dp = (const float4*)drop;
        for (int g0 = cw * 4; g0 < NGRP; g0 += 2368 * 4) {
            float4 vv[4];
            #pragma unroll
            for (int q = 0; q < 4; q++) {          // warp-uniform guards
                if (g0 + q < NGRP)
                    vv[q] = __ldcs(dp + (size_t)(g0 + q) * 32 + lane);
            }
            #pragma unroll
            for (int q = 0; q < 4; q++) {
                if (g0 + q < NGRP) {
                    const unsigned b0 = __ballot_sync(0xFFFFFFFFu, vv[q].x != 0.f);
                    const unsigned b1 = __ballot_sync(0xFFFFFFFFu, vv[q].y != 0.f);
                    const unsigned b2 = __ballot_sync(0xFFFFFFFFu, vv[q].z != 0.f);
                    const unsigned b3 = __ballot_sync(0xFFFFFFFFu, vv[q].w != 0.f);
                    if (lane == 0) g_mb[g0 + q] = make_uint4(b0, b1, b2, b3);
                }
            }
        }
        return;
    }

    // ---- GEMM role ----
    const float2* wm2 = (const float2*)wm;
    for (int i = tid; i < FDIM * 32; i += blockDim.x) {
        sT[i] = wm2[i];
        sB[i] = wm2[FDIM * 32 + i];
    }
    __syncthreads();

    const int gw = (int)(blockIdx.x >> 1) * 8 + wsub;
    const int chunk = lane >> 1, pos = lane & 1;
    const float2* x2 = (const float2*)x;

    for (int c = gw; c < NN / 8; c += 2368) {
        const int base = c * 8;
        #pragma unroll
        for (int r = 0; r < 8; r++)
            ((float2*)sx[wsub][r])[lane] = x2[(base + r) * 32 + lane];
        __syncwarp();

        unsigned long long tA[8], bA[8];
        #pragma unroll
        for (int r = 0; r < 8; r++) { tA[r] = 0ull; bA[r] = 0ull; }

        #pragma unroll 8
        for (int k = 0; k < FDIM; k++) {
            unsigned long long wt, wb;
            memcpy(&wt, &sT[k * 32 + lane], 8);
            memcpy(&wb, &sB[k * 32 + lane], 8);
            #pragma unroll
            for (int r = 0; r < 8; r++) {
                const unsigned long long xk = pack2(sx[wsub][r][k]);
                fma2(tA[r], xk, wt);
                fma2(bA[r], xk, wb);
            }
        }
        #pragma unroll
        for (int r = 0; r < 8; r++) {
            g_Th[(base + r) * 32 + lane] = __float22half2_rn(unpack2(tA[r]));
            const float2 bP = unpack2(bA[r]);
            const float2 xP = ((float2*)sx[wsub][r])[lane];
            __half2* rec = (__half2*)&g_bxh[(base + r) * 16];
            rec[chunk * 4 + pos]     = __float22half2_rn(bP);
            rec[chunk * 4 + 2 + pos] = __float22half2_rn(xP);
        }
        __syncwarp();
    }
}

// ---------------------------------------------------------------------------
// K2: x_new[n] = x[n] + sum_d sigmoid(T[n]+B[j]) * drop_bit*2 * x[j]
// Half-warp per node. drop comes from the 6.4 MB bitmask (broadcast 16B
// loads); B+x from one fp16 16B gather per edge-lane, 8-deep prefetched.
// ---------------------------------------------------------------------------
__global__ __launch_bounds__(256, 2)
void k_edge(const float* __restrict__ x)
{
    const int tid  = threadIdx.x;
    const int lane = tid & 31;
    const int hl   = lane >> 4;          // which node of the pair
    const int fl   = lane & 15;          // float4 slot (features 4fl..4fl+3)
    const int gw   = blockIdx.x * 8 + (tid >> 5);
    const int nwarps = gridDim.x * 8;

    const float4* x4 = (const float4*)x;

    for (int c = gw; c < NN / 2; c += nwarps) {
        const int n = c * 2 + hl;

        // T fp16 -> float4
        uint2 tv;
        memcpy(&tv, &g_Th[n * 32 + 2 * fl], 8);
        const float2 t01 = __half22float2(*(const __half2*)&tv.x);
        const float2 t23 = __half22float2(*(const __half2*)&tv.y);
        const float4 t = make_float4(t01.x, t01.y, t23.x, t23.y);

        float4 a = x4[n * 16 + fl];

        int js[DEG];
        {
            const int4* nb4 = (const int4*)(g_nbr + n * DEG);
            #pragma unroll
            for (int q = 0; q < 4; q++) *(int4*)&js[q * 4] = nb4[q];
        }

        #pragma unroll
        for (int half = 0; half < 2; half++) {
            // bitmask words for edges d = half*8 .. half*8+7  (broadcast loads)
            uint4 bb[4];
            #pragma unroll
            for (int q = 0; q < 4; q++)
                bb[q] = g_mb[n * 8 + half * 4 + q];
            // front-batch 8 record gathers (MLP = 8)
            uint4 gbuf[8];
            #pragma unroll
            for (int q = 0; q < 8; q++)
                gbuf[q] = g_bxh[js[half * 8 + q] * 16 + fl];

            #pragma unroll
            for (int q = 0; q < 8; q++) {
                const __half2* hv = (const __half2*)&gbuf[q];
                const float2 b01 = __half22float2(hv[0]);
                const float2 b23 = __half22float2(hv[1]);
                const float2 x01 = __half22float2(hv[2]);
                const float2 x23 = __half22float2(hv[3]);
                const uint4 bw = bb[q >> 1];
                const int idx = fl + ((q & 1) << 4);
                const float mx = ((bw.x >> idx) & 1u) ? 2.0f : 0.0f;
                const float my = ((bw.y >> idx) & 1u) ? 2.0f : 0.0f;
                const float mz = ((bw.z >> idx) & 1u) ? 2.0f : 0.0f;
                const float mw = ((bw.w >> idx) & 1u) ? 2.0f : 0.0f;
                a.x += sigmoid_fast(t.x + b01.x) * mx * x01.x;
                a.y += sigmoid_fast(t.y + b01.y) * my * x01.y;
                a.z += sigmoid_fast(t.z + b23.x) * mz * x23.x;
                a.w += sigmoid_fast(t.w + b23.y) * mw * x23.y;
            }
        }
        uint2 st;
        *(__half2*)&st.x = __float22half2_rn(make_float2(a.x, a.y));
        *(__half2*)&st.y = __float22half2_rn(make_float2(a.z, a.w));
        g_xnh[n * 16 + fl] = st;
    }
}

// ---------------------------------------------------------------------------
// K34 (fused): agg[n] = sum_d adj[n,d]*x_new[nbr[n,d]] (fp16 gather) staged
// into shared, then out = agg @ weight_0 + bias (8 rows/warp, f32x2). 3 CTAs.
// ---------------------------------------------------------------------------
__global__ __launch_bounds__(256, 3)
void k_agg_gemm(const float* __restrict__ adj, const float* __restrict__ w0,
                const float* __restrict__ bias, float* __restrict__ out)
{
    __shared__ float2 sW[FDIM * 32];
    __shared__ float  sx[8][8][FDIM];

    const int tid = threadIdx.x;
    const float2* w02 = (const float2*)w0;
    for (int i = tid; i < FDIM * 32; i += blockDim.x) sW[i] = w02[i];
    __syncthreads();

    const int lane = tid & 31, wsub = tid >> 5;
    const int hl = lane >> 4, fl = lane & 15;
    const int gw = blockIdx.x * 8 + wsub;
    const int nwarps = gridDim.x * 8;

    const float2 bi = ((const float2*)bias)[lane];
    unsigned long long biP;
    memcpy(&biP, &bi, 8);

    for (int c = gw; c < NN / 8; c += nwarps) {
        const int base = c * 8;

        #pragma unroll
        for (int p = 0; p < 4; p++) {
            const int n = base + 2 * p + hl;
            float aj[DEG];
            int js[DEG];
            {
                const float4* a4 = (const float4*)(adj + (size_t)n * DEG);
                const int4* nb4 = (const int4*)(g_nbr + n * DEG);
                #pragma unroll
                for (int q = 0; q < 4; q++) {
                    *(float4*)&aj[q * 4] = __ldcs(a4 + q);
                    *(int4*)&js[q * 4]   = nb4[q];
                }
            }
            float4 acc = make_float4(0.f, 0.f, 0.f, 0.f);
            #pragma unroll
            for (int d = 0; d < DEG; d++) {
                const uint2 sv = g_xnh[js[d] * 16 + fl];
                const float2 s01 = __half22float2(*(const __half2*)&sv.x);
                const float2 s23 = __half22float2(*(const __half2*)&sv.y);
                acc.x += aj[d] * s01.x;  acc.y += aj[d] * s01.y;
                acc.z += aj[d] * s23.x;  acc.w += aj[d] * s23.y;
            }
            *(float4*)&sx[wsub][2 * p + hl][fl * 4] = acc;
        }
        __syncwarp();

        unsigned long long o[8];
        #pragma unroll
        for (int r = 0; r < 8; r++) o[r] = biP;

        #pragma unroll 8
        for (int k = 0; k < FDIM; k++) {
            unsigned long long wv;
            memcpy(&wv, &sW[k * 32 + lane], 8);
            #pragma unroll
            for (int r = 0; r < 8; r++)
                fma2(o[r], pack2(sx[wsub][r][k]), wv);
        }
        #pragma unroll
        for (int r = 0; r < 8; r++)
            ((float2*)out)[(base + r) * 32 + lane] = unpack2(o[r]);
        __syncwarp();
    }
}

// ---------------------------------------------------------------------------
extern "C" void kernel_launch(void* const* d_in, const int* in_sizes, int n_in,
                              void* d_out, int out_size)
{
    const float* x    = (const float*)d_in[0];
    const float* w0   = (const float*)d_in[1];
    const float* wm   = (const float*)d_in[2];
    const float* bias = (const float*)d_in[3];
    const float* adj  = (const float*)d_in[4];
    const float* drop = (const float*)d_in[5];
    const int*   nbrr = (const int*)d_in[6];
    float* out = (float*)d_out;

    k_detect  <<<64, 256>>>(nbrr);
    k_convert <<<148, 256>>>(nbrr);
    k_prep    <<<592, 256>>>(x, wm, drop);
    k_edge    <<<592, 256>>>(x);
    k_agg_gemm<<<444, 256>>>(adj, w0, bias, out);
}

// round 15
// speedup vs baseline: 1.5785x; 1.5785x over previous
#include <cuda_runtime.h>
#include <cuda_fp16.h>
#include <cstdint>
#include <cstring>

#define NN   50000
#define DEG  16
#define FDIM 64
#define NE   (NN * DEG)

// Scratch (allocation-free rule)
__device__ __align__(16) __half2 g_Th[NN * 32];  // T fp16 (lane l: feats 2l,2l+1)
__device__ __align__(16) uint4  g_bxh[NN * 16];  // fp16 {B,x} 16B chunks per node
__device__ __align__(16) uint2  g_xnh[NN * 16];  // x_new fp16
__device__ __align__(16) int    g_nbr[NE];
__device__ int g_is32 = 0;

// ---- packed f32x2 helpers (Blackwell) -------------------------------------
__device__ __forceinline__ unsigned long long pack2(float v) {
    unsigned long long r;
    asm("mov.b64 %0, {%1, %1};" : "=l"(r) : "f"(v));
    return r;
}
__device__ __forceinline__ void fma2(unsigned long long& d,
                                     unsigned long long a, unsigned long long b) {
    asm("fma.rn.f32x2 %0, %1, %2, %0;" : "+l"(d) : "l"(a), "l"(b));
}
__device__ __forceinline__ float2 unpack2(unsigned long long v) {
    float2 f;
    asm("mov.b64 {%0, %1}, %2;" : "=f"(f.x), "=f"(f.y) : "l"(v));
    return f;
}
__device__ __forceinline__ float sigmoid_fast(float z) {
    float t;
    asm("tanh.approx.f32 %0, %1;" : "=f"(t) : "f"(0.5f * z));
    return fmaf(0.5f, t, 0.5f);
}

// ---------------------------------------------------------------------------
// K0: dtype sniff. int64 (LE, vals < 2^31) => odd 32-bit words all zero.
// 8192 odd words scanned (conclusive: P[int32 all-zero] ~ (1/5e4)^8192).
// Warp-any + plain idempotent store — NO same-address atomic storm.
// ---------------------------------------------------------------------------
__global__ void k_detect(const int* __restrict__ raw)
{
    const int t = blockIdx.x * blockDim.x + threadIdx.x;   // 0..8191
    int nz = 0;
    if (t < 8192) nz = (raw[2 * t + 1] != 0);
    if (__any_sync(0xFFFFFFFFu, nz) && (threadIdx.x & 31) == 0)
        g_is32 = 1;
}

// ---------------------------------------------------------------------------
// K1: T = x@wm_top (fp16 out); g_bxh[n] = fp16 {B,x} records.
// Also folds the index convert (10 MB stream rides under the FFMA compute).
// 8 rows/warp amortized weights, f32x2 FMA.
// ---------------------------------------------------------------------------
__global__ __launch_bounds__(256, 2)
void k_gemm_tb(const float* __restrict__ x, const float* __restrict__ wm,
               const int* __restrict__ raw)
{
    __shared__ float2 sT[FDIM * 32];
    __shared__ float2 sB[FDIM * 32];
    __shared__ float  sx[8][8][FDIM];     // [warp][row][k]

    const int tid = threadIdx.x;

    // ---- folded convert: g_nbr[i] = int32 view of nbr_idx ----
    {
        const int is32 = g_is32;
        const int gt = blockIdx.x * blockDim.x + tid;
        const int nthr = gridDim.x * blockDim.x;
        if (is32) {
            for (int i = gt; i < NE; i += nthr) g_nbr[i] = raw[i];
        } else {
            for (int i = gt; i < NE; i += nthr) g_nbr[i] = raw[2 * i];
        }
    }

    const float2* wm2 = (const float2*)wm;
    for (int i = tid; i < FDIM * 32; i += blockDim.x) {
        sT[i] = wm2[i];
        sB[i] = wm2[FDIM * 32 + i];
    }
    __syncthreads();

    const int lane = tid & 31, wsub = tid >> 5;
    const int gw = blockIdx.x * 8 + wsub;
    const int nwarps = gridDim.x * 8;
    const float2* x2 = (const float2*)x;
    const int chunk = lane >> 1, pos = lane & 1;

    for (int c = gw; c < NN / 8; c += nwarps) {
        const int base = c * 8;
        #pragma unroll
        for (int r = 0; r < 8; r++)
            ((float2*)sx[wsub][r])[lane] = x2[(base + r) * 32 + lane];
        __syncwarp();

        unsigned long long tA[8], bA[8];
        #pragma unroll
        for (int r = 0; r < 8; r++) { tA[r] = 0ull; bA[r] = 0ull; }

        #pragma unroll 8
        for (int k = 0; k < FDIM; k++) {
            unsigned long long wt, wb;
            memcpy(&wt, &sT[k * 32 + lane], 8);
            memcpy(&wb, &sB[k * 32 + lane], 8);
            #pragma unroll
            for (int r = 0; r < 8; r++) {
                const unsigned long long xk = pack2(sx[wsub][r][k]);
                fma2(tA[r], xk, wt);
                fma2(bA[r], xk, wb);
            }
        }
        #pragma unroll
        for (int r = 0; r < 8; r++) {
            g_Th[(base + r) * 32 + lane] = __float22half2_rn(unpack2(tA[r]));
            const float2 bP = unpack2(bA[r]);
            const float2 xP = ((float2*)sx[wsub][r])[lane];
            __half2* rec = (__half2*)&g_bxh[(base + r) * 16];
            rec[chunk * 4 + pos]     = __float22half2_rn(bP);
            rec[chunk * 4 + 2 + pos] = __float22half2_rn(xP);
        }
        __syncwarp();
    }
}

// ---------------------------------------------------------------------------
// K2: x_new[n] = x[n] + sum_d sigmoid(T[n]+B[j])*drop[n,d]*x[j]
// Half-warp per node, float4 lanes, 2 CTAs/128 regs. drop streamed in-kernel
// (reads it exactly once — splitting it out was measured as a net loss).
// One 16B fp16 gather per edge-lane; 8-deep explicit drop prefetch.
// ---------------------------------------------------------------------------
__global__ __launch_bounds__(256, 2)
void k_edge(const float* __restrict__ x, const float* __restrict__ drop)
{
    const int tid  = threadIdx.x;
    const int lane = tid & 31;
    const int hl   = lane >> 4;          // which node of the pair
    const int fl   = lane & 15;          // float4 slot (features 4fl..4fl+3)
    const int gw   = blockIdx.x * 8 + (tid >> 5);
    const int nwarps = gridDim.x * 8;

    const float4* x4 = (const float4*)x;

    for (int c = gw; c < NN / 2; c += nwarps) {
        const int n = c * 2 + hl;

        uint2 tv;
        memcpy(&tv, &g_Th[n * 32 + 2 * fl], 8);
        const float2 t01 = __half22float2(*(const __half2*)&tv.x);
        const float2 t23 = __half22float2(*(const __half2*)&tv.y);
        const float4 t = make_float4(t01.x, t01.y, t23.x, t23.y);

        float4 a = x4[n * 16 + fl];

        int js[DEG];
        {
            const int4* nb4 = (const int4*)(g_nbr + n * DEG);
            #pragma unroll
            for (int q = 0; q < 4; q++) *(int4*)&js[q * 4] = nb4[q];
        }
        const float4* dm = (const float4*)(drop + (size_t)n * DEG * FDIM);

        float4 mbuf[8];
        #pragma unroll
        for (int half = 0; half < 2; half++) {
            const int d0 = half * 8;
            #pragma unroll
            for (int q = 0; q < 8; q++)
                mbuf[q] = __ldcs(dm + (d0 + q) * 16 + fl);
            #pragma unroll
            for (int q = 0; q < 8; q++) {
                const int j = js[d0 + q];
                const uint4 v = g_bxh[j * 16 + fl];
                const __half2* hv = (const __half2*)&v;
                const float2 b01 = __half22float2(hv[0]);
                const float2 b23 = __half22float2(hv[1]);
                const float2 x01 = __half22float2(hv[2]);
                const float2 x23 = __half22float2(hv[3]);
                const float4 m = mbuf[q];
                a.x += sigmoid_fast(t.x + b01.x) * m.x * x01.x;
                a.y += sigmoid_fast(t.y + b01.y) * m.y * x01.y;
                a.z += sigmoid_fast(t.z + b23.x) * m.z * x23.x;
                a.w += sigmoid_fast(t.w + b23.y) * m.w * x23.y;
            }
        }
        uint2 st;
        *(__half2*)&st.x = __float22half2_rn(make_float2(a.x, a.y));
        *(__half2*)&st.y = __float22half2_rn(make_float2(a.z, a.w));
        g_xnh[n * 16 + fl] = st;
    }
}

// ---------------------------------------------------------------------------
// K34 (fused): agg[n] = sum_d adj[n,d]*x_new[nbr[n,d]] (fp16 gather) staged
// into shared, then out = agg @ weight_0 + bias (8 rows/warp, f32x2). 3 CTAs.
// ---------------------------------------------------------------------------
__global__ __launch_bounds__(256, 3)
void k_agg_gemm(const float* __restrict__ adj, const float* __restrict__ w0,
                const float* __restrict__ bias, float* __restrict__ out)
{
    __shared__ float2 sW[FDIM * 32];
    __shared__ float  sx[8][8][FDIM];

    const int tid = threadIdx.x;
    const float2* w02 = (const float2*)w0;
    for (int i = tid; i < FDIM * 32; i += blockDim.x) sW[i] = w02[i];
    __syncthreads();

    const int lane = tid & 31, wsub = tid >> 5;
    const int hl = lane >> 4, fl = lane & 15;
    const int gw = blockIdx.x * 8 + wsub;
    const int nwarps = gridDim.x * 8;

    const float2 bi = ((const float2*)bias)[lane];
    unsigned long long biP;
    memcpy(&biP, &bi, 8);

    for (int c = gw; c < NN / 8; c += nwarps) {
        const int base = c * 8;

        #pragma unroll
        for (int p = 0; p < 4; p++) {
            const int n = base + 2 * p + hl;
            float aj[DEG];
            int js[DEG];
            {
                const float4* a4 = (const float4*)(adj + (size_t)n * DEG);
                const int4* nb4 = (const int4*)(g_nbr + n * DEG);
                #pragma unroll
                for (int q = 0; q < 4; q++) {
                    *(float4*)&aj[q * 4] = __ldcs(a4 + q);
                    *(int4*)&js[q * 4]   = nb4[q];
                }
            }
            float4 acc = make_float4(0.f, 0.f, 0.f, 0.f);
            #pragma unroll
            for (int d = 0; d < DEG; d++) {
                const uint2 sv = g_xnh[js[d] * 16 + fl];
                const float2 s01 = __half22float2(*(const __half2*)&sv.x);
                const float2 s23 = __half22float2(*(const __half2*)&sv.y);
                acc.x += aj[d] * s01.x;  acc.y += aj[d] * s01.y;
                acc.z += aj[d] * s23.x;  acc.w += aj[d] * s23.y;
            }
            *(float4*)&sx[wsub][2 * p + hl][fl * 4] = acc;
        }
        __syncwarp();

        unsigned long long o[8];
        #pragma unroll
        for (int r = 0; r < 8; r++) o[r] = biP;

        #pragma unroll 8
        for (int k = 0; k < FDIM; k++) {
            unsigned long long wv;
            memcpy(&wv, &sW[k * 32 + lane], 8);
            #pragma unroll
            for (int r = 0; r < 8; r++)
                fma2(o[r], pack2(sx[wsub][r][k]), wv);
        }
        #pragma unroll
        for (int r = 0; r < 8; r++)
            ((float2*)out)[(base + r) * 32 + lane] = unpack2(o[r]);
        __syncwarp();
    }
}

// ---------------------------------------------------------------------------
extern "C" void kernel_launch(void* const* d_in, const int* in_sizes, int n_in,
                              void* d_out, int out_size)
{
    const float* x    = (const float*)d_in[0];
    const float* w0   = (const float*)d_in[1];
    const float* wm   = (const float*)d_in[2];
    const float* bias = (const float*)d_in[3];
    const float* adj  = (const float*)d_in[4];
    const float* drop = (const float*)d_in[5];
    const int*   nbrr = (const int*)d_in[6];
    float* out = (float*)d_out;

    k_detect  <<<32, 256>>>(nbrr);
    k_gemm_tb <<<296, 256>>>(x, wm, nbrr);
    k_edge    <<<592, 256>>>(x, drop);
    k_agg_gemm<<<444, 256>>>(adj, w0, bias, out);
}

// round 17
// speedup vs baseline: 1.7477x; 1.1072x over previous
#include <cuda_runtime.h>
#include <cuda_fp16.h>
#include <cstdint>
#include <cstring>

#define NN   50000
#define DEG  16
#define FDIM 64
#define NE   (NN * DEG)

// Scratch (allocation-free rule)
__device__ __align__(16) __half2 g_Th[NN * 32];  // T fp16 (lane l: feats 2l,2l+1)
__device__ __align__(16) uint4  g_bxh[NN * 16];  // fp16 {B,x} 16B chunks per node
__device__ __align__(16) uint2  g_xnh[NN * 16];  // x_new fp16
__device__ __align__(16) int    g_nbr[NE];
__device__ int g_is32 = 0;

// ---- packed f32x2 helpers (Blackwell) -------------------------------------
__device__ __forceinline__ unsigned long long pack2(float v) {
    unsigned long long r;
    asm("mov.b64 %0, {%1, %1};" : "=l"(r) : "f"(v));
    return r;
}
__device__ __forceinline__ void fma2(unsigned long long& d,
                                     unsigned long long a, unsigned long long b) {
    asm("fma.rn.f32x2 %0, %1, %2, %0;" : "+l"(d) : "l"(a), "l"(b));
}
__device__ __forceinline__ float2 unpack2(unsigned long long v) {
    float2 f;
    asm("mov.b64 {%0, %1}, %2;" : "=f"(f.x), "=f"(f.y) : "l"(v));
    return f;
}
__device__ __forceinline__ float sigmoid_fast(float z) {
    float t;
    asm("tanh.approx.f32 %0, %1;" : "=f"(t) : "f"(0.5f * z));
    return fmaf(0.5f, t, 0.5f);
}
__device__ __forceinline__ uint32_t smem_u32(const void* p) {
    uint32_t a;
    asm("{ .reg .u64 t; cvta.to.shared.u64 t, %1; cvt.u32.u64 %0, t; }"
        : "=r"(a) : "l"(p));
    return a;
}

// ---------------------------------------------------------------------------
// K0: dtype sniff (8192 odd words; warp-any + idempotent plain store)
// ---------------------------------------------------------------------------
__global__ void k_detect(const int* __restrict__ raw)
{
    const int t = blockIdx.x * blockDim.x + threadIdx.x;   // 0..8191
    int nz = 0;
    if (t < 8192) nz = (raw[2 * t + 1] != 0);
    if (__any_sync(0xFFFFFFFFu, nz) && (threadIdx.x & 31) == 0)
        g_is32 = 1;
}

// ---------------------------------------------------------------------------
// K1: T = x@wm_top (fp16 out); g_bxh[n] = fp16 {B,x} records.
// Folds index convert. 8 rows/warp amortized weights, f32x2 FMA.
// ---------------------------------------------------------------------------
__global__ __launch_bounds__(256, 2)
void k_gemm_tb(const float* __restrict__ x, const float* __restrict__ wm,
               const int* __restrict__ raw)
{
    __shared__ float2 sT[FDIM * 32];
    __shared__ float2 sB[FDIM * 32];
    __shared__ float  sx[8][8][FDIM];

    const int tid = threadIdx.x;

    {   // folded convert
        const int is32 = g_is32;
        const int gt = blockIdx.x * blockDim.x + tid;
        const int nthr = gridDim.x * blockDim.x;
        if (is32) {
            for (int i = gt; i < NE; i += nthr) g_nbr[i] = raw[i];
        } else {
            for (int i = gt; i < NE; i += nthr) g_nbr[i] = raw[2 * i];
        }
    }

    const float2* wm2 = (const float2*)wm;
    for (int i = tid; i < FDIM * 32; i += blockDim.x) {
        sT[i] = wm2[i];
        sB[i] = wm2[FDIM * 32 + i];
    }
    __syncthreads();

    const int lane = tid & 31, wsub = tid >> 5;
    const int gw = blockIdx.x * 8 + wsub;
    const int nwarps = gridDim.x * 8;
    const float2* x2 = (const float2*)x;
    const int chunk = lane >> 1, pos = lane & 1;

    for (int c = gw; c < NN / 8; c += nwarps) {
        const int base = c * 8;
        #pragma unroll
        for (int r = 0; r < 8; r++)
            ((float2*)sx[wsub][r])[lane] = x2[(base + r) * 32 + lane];
        __syncwarp();

        unsigned long long tA[8], bA[8];
        #pragma unroll
        for (int r = 0; r < 8; r++) { tA[r] = 0ull; bA[r] = 0ull; }

        #pragma unroll 8
        for (int k = 0; k < FDIM; k++) {
            unsigned long long wt, wb;
            memcpy(&wt, &sT[k * 32 + lane], 8);
            memcpy(&wb, &sB[k * 32 + lane], 8);
            #pragma unroll
            for (int r = 0; r < 8; r++) {
                const unsigned long long xk = pack2(sx[wsub][r][k]);
                fma2(tA[r], xk, wt);
                fma2(bA[r], xk, wb);
            }
        }
        #pragma unroll
        for (int r = 0; r < 8; r++) {
            g_Th[(base + r) * 32 + lane] = __float22half2_rn(unpack2(tA[r]));
            const float2 bP = unpack2(bA[r]);
            const float2 xP = ((float2*)sx[wsub][r])[lane];
            __half2* rec = (__half2*)&g_bxh[(base + r) * 16];
            rec[chunk * 4 + pos]     = __float22half2_rn(bP);
            rec[chunk * 4 + 2 + pos] = __float22half2_rn(xP);
        }
        __syncwarp();
    }
}

// ---------------------------------------------------------------------------
// K2: x_new = x + sum_d sigmoid(T+B[j])*drop*x[j].  (LTS-cap bound; final.)
// ---------------------------------------------------------------------------
__global__ __launch_bounds__(256, 2)
void k_edge(const float* __restrict__ x, const float* __restrict__ drop)
{
    const int tid  = threadIdx.x;
    const int lane = tid & 31;
    const int hl   = lane >> 4;
    const int fl   = lane & 15;
    const int gw   = blockIdx.x * 8 + (tid >> 5);
    const int nwarps = gridDim.x * 8;

    const float4* x4 = (const float4*)x;

    for (int c = gw; c < NN / 2; c += nwarps) {
        const int n = c * 2 + hl;

        uint2 tv;
        memcpy(&tv, &g_Th[n * 32 + 2 * fl], 8);
        const float2 t01 = __half22float2(*(const __half2*)&tv.x);
        const float2 t23 = __half22float2(*(const __half2*)&tv.y);
        const float4 t = make_float4(t01.x, t01.y, t23.x, t23.y);

        float4 a = x4[n * 16 + fl];

        int js[DEG];
        {
            const int4* nb4 = (const int4*)(g_nbr + n * DEG);
            #pragma unroll
            for (int q = 0; q < 4; q++) *(int4*)&js[q * 4] = nb4[q];
        }
        const float4* dm = (const float4*)(drop + (size_t)n * DEG * FDIM);

        float4 mbuf[8];
        #pragma unroll
        for (int half = 0; half < 2; half++) {
            const int d0 = half * 8;
            #pragma unroll
            for (int q = 0; q < 8; q++)
                mbuf[q] = __ldcs(dm + (d0 + q) * 16 + fl);
            #pragma unroll
            for (int q = 0; q < 8; q++) {
                const int j = js[d0 + q];
                const uint4 v = g_bxh[j * 16 + fl];
                const __half2* hv = (const __half2*)&v;
                const float2 b01 = __half22float2(hv[0]);
                const float2 b23 = __half22float2(hv[1]);
                const float2 x01 = __half22float2(hv[2]);
                const float2 x23 = __half22float2(hv[3]);
                const float4 m = mbuf[q];
                a.x += sigmoid_fast(t.x + b01.x) * m.x * x01.x;
                a.y += sigmoid_fast(t.y + b01.y) * m.y * x01.y;
                a.z += sigmoid_fast(t.z + b23.x) * m.z * x23.x;
                a.w += sigmoid_fast(t.w + b23.y) * m.w * x23.y;
            }
        }
        uint2 st;
        *(__half2*)&st.x = __float22half2_rn(make_float2(a.x, a.y));
        *(__half2*)&st.y = __float22half2_rn(make_float2(a.z, a.w));
        g_xnh[n * 16 + fl] = st;
    }
}

// ---------------------------------------------------------------------------
// K34: phase A gathers agg[16 rows] into per-warp fp16 smem tile; phase B
// does out = agg @ W0 + bias via mma.sync.m16n8k16 (fp16 in, fp32 acc).
// Warp-tile = 16 nodes; one tile per warp at grid 392.
// ---------------------------------------------------------------------------
#define SXP 72   // padded row stride (halves): 144B -> 4-bank stagger
__global__ __launch_bounds__(256, 3)
void k_agg_gemm(const float* __restrict__ adj, const float* __restrict__ w0,
                const float* __restrict__ bias, float* __restrict__ out)
{
    __shared__ __half sW[FDIM][SXP];      // W0 fp16 [k][n]
    __shared__ __half sxh[8][16][SXP];    // per-warp agg tiles [row][k]
    __shared__ float  sBias[FDIM];

    const int tid = threadIdx.x;
    // convert W0 -> fp16 smem; bias -> smem
    for (int i = tid; i < FDIM * FDIM; i += blockDim.x)
        sW[i >> 6][i & 63] = __float2half_rn(w0[i]);
    if (tid < FDIM) sBias[tid] = bias[tid];
    __syncthreads();

    const int lane = tid & 31, wsub = tid >> 5;
    const int hl = lane >> 4, fl = lane & 15;
    const int gw = blockIdx.x * 8 + wsub;
    const int nwarps = gridDim.x * 8;

    const uint32_t sx_base = smem_u32(&sxh[wsub][0][0]);
    const uint32_t sw_base = smem_u32(&sW[0][0]);

    for (int tile = gw; tile < NN / 16; tile += nwarps) {
        const int base = tile * 16;

        // ---- Phase A: aggregate 16 nodes (2 per pass, half-warp each) ----
        #pragma unroll
        for (int p = 0; p < 8; p++) {
            const int n = base + 2 * p + hl;
            float aj[DEG];
            int js[DEG];
            {
                const float4* a4 = (const float4*)(adj + (size_t)n * DEG);
                const int4* nb4 = (const int4*)(g_nbr + n * DEG);
                #pragma unroll
                for (int q = 0; q < 4; q++) {
                    *(float4*)&aj[q * 4] = __ldcs(a4 + q);
                    *(int4*)&js[q * 4]   = nb4[q];
                }
            }
            float4 acc = make_float4(0.f, 0.f, 0.f, 0.f);
            #pragma unroll
            for (int d = 0; d < DEG; d++) {
                const uint2 sv = g_xnh[js[d] * 16 + fl];
                const float2 s01 = __half22float2(*(const __half2*)&sv.x);
                const float2 s23 = __half22float2(*(const __half2*)&sv.y);
                acc.x += aj[d] * s01.x;  acc.y += aj[d] * s01.y;
                acc.z += aj[d] * s23.x;  acc.w += aj[d] * s23.y;
            }
            uint2 st;
            *(__half2*)&st.x = __float22half2_rn(make_float2(acc.x, acc.y));
            *(__half2*)&st.y = __float22half2_rn(make_float2(acc.z, acc.w));
            *(uint2*)&sxh[wsub][2 * p + hl][fl * 4] = st;
        }
        __syncwarp();

        // ---- Phase B: 16x64 @ 64x64 via mma.m16n8k16 ----
        uint32_t A[4][4];
        #pragma unroll
        for (int kt = 0; kt < 4; kt++) {
            const uint32_t addr = sx_base + (lane & 15) * (SXP * 2)
                                + kt * 32 + (lane >> 4) * 16;
            asm volatile(
                "ldmatrix.sync.aligned.m8n8.x4.shared.b16 {%0,%1,%2,%3}, [%4];"
                : "=r"(A[kt][0]), "=r"(A[kt][1]), "=r"(A[kt][2]), "=r"(A[kt][3])
                : "r"(addr));
        }

        #pragma unroll
        for (int nt = 0; nt < 8; nt++) {
            float2 bv;
            memcpy(&bv, &sBias[nt * 8 + (lane & 3) * 2], 8);
            float d0 = bv.x, d1 = bv.y, d2 = bv.x, d3 = bv.y;

            #pragma unroll
            for (int kt = 0; kt < 4; kt++) {
                uint32_t b0, b1;
                const uint32_t baddr = sw_base
                    + (kt * 16 + (lane & 15)) * (SXP * 2) + nt * 16;
                asm volatile(
                    "ldmatrix.sync.aligned.m8n8.x2.trans.shared.b16 {%0,%1}, [%2];"
                    : "=r"(b0), "=r"(b1) : "r"(baddr));
                asm volatile(
                    "mma.sync.aligned.m16n8k16.row.col.f32.f16.f16.f32 "
                    "{%0,%1,%2,%3}, {%4,%5,%6,%7}, {%8,%9}, {%0,%1,%2,%3};"
                    : "+f"(d0), "+f"(d1), "+f"(d2), "+f"(d3)
                    : "r"(A[kt][0]), "r"(A[kt][1]), "r"(A[kt][2]), "r"(A[kt][3]),
                      "r"(b0), "r"(b1));
            }

            const int r0 = lane >> 2;
            const int c0 = nt * 8 + (lane & 3) * 2;
            float2 o01 = make_float2(d0, d1);
            float2 o23 = make_float2(d2, d3);
            *(float2*)&out[(size_t)(base + r0) * FDIM + c0]     = o01;
            *(float2*)&out[(size_t)(base + r0 + 8) * FDIM + c0] = o23;
        }
        __syncwarp();
    }
}

// ---------------------------------------------------------------------------
extern "C" void kernel_launch(void* const* d_in, const int* in_sizes, int n_in,
                              void* d_out, int out_size)
{
    const float* x    = (const float*)d_in[0];
    const float* w0   = (const float*)d_in[1];
    const float* wm   = (const float*)d_in[2];
    const float* bias = (const float*)d_in[3];
    const float* adj  = (const float*)d_in[4];
    const float* drop = (const float*)d_in[5];
    const int*   nbrr = (const int*)d_in[6];
    float* out = (float*)d_out;

    k_detect  <<<32, 256>>>(nbrr);
    k_gemm_tb <<<296, 256>>>(x, wm, nbrr);
    k_edge    <<<592, 256>>>(x, drop);
    k_agg_gemm<<<392, 256>>>(adj, w0, bias, out);
}